// round 1
// baseline (speedup 1.0000x reference)
#include <cuda_runtime.h>
#include <cstdint>

// Problem constants
#define T_TOK  2048      // tokens
#define N_NEU  11008     // neurons (K dim of GEMM, columns of weight)
#define D_OUT  4096      // output dim (rows of weight)
#define K_TOK  2201      // int(11008 * 0.2)
#define N_CORE 4403      // int(11008 * 0.4)

// -------- device scratch (no allocations allowed) --------
__device__ int g_counts[N_NEU];
__device__ int g_hist[2049];     // counts take values 0..2048
__device__ int g_off[2049];
__device__ int g_core_idx[N_CORE];

// order-preserving float -> uint map (ascending)
__device__ __forceinline__ unsigned int fkey(float f) {
    unsigned int u = __float_as_uint(f);
    return (u & 0x80000000u) ? ~u : (u | 0x80000000u);
}

// -------- reset scratch each launch (graph-replay safe) --------
__global__ void zero_kernel() {
    int i = blockIdx.x * blockDim.x + threadIdx.x;
    if (i < N_NEU) g_counts[i] = 0;
    if (i < 2049)  g_hist[i] = 0;
}

// -------- per-token exact top-K threshold (3-level MSB radix select) + vote count --------
// Exactly replicates jax.lax.top_k semantics: exactly K_TOK elements per token,
// ties at the threshold value broken by LOWEST index first.
__global__ void topk_count_kernel(const float* __restrict__ X) {
    __shared__ unsigned int h[2048];
    __shared__ unsigned int s_prefix;
    __shared__ int s_k;
    __shared__ int s_eq_n;
    __shared__ int s_eq_idx[64];

    const int t = blockIdx.x;
    const float* row = X + (size_t)t * N_NEU;

    if (threadIdx.x == 0) { s_prefix = 0u; s_k = K_TOK; s_eq_n = 0; }

    #pragma unroll
    for (int p = 0; p < 3; p++) {
        const int shift = (p == 0) ? 21 : (p == 1) ? 10 : 0;
        const int nbins = (p == 2) ? 1024 : 2048;
        const unsigned int himask =
            (p == 0) ? 0u : ((p == 1) ? (0xFFFFFFFFu << 21) : (0xFFFFFFFFu << 10));

        for (int i = threadIdx.x; i < nbins; i += blockDim.x) h[i] = 0u;
        __syncthreads();

        const unsigned int pre = s_prefix;
        for (int i = threadIdx.x; i < N_NEU; i += blockDim.x) {
            unsigned int u = fkey(row[i]);
            if ((u & himask) == pre)
                atomicAdd(&h[(u >> shift) & (unsigned)(nbins - 1)], 1u);
        }
        __syncthreads();

        if (threadIdx.x == 0) {
            int k = s_k;
            int cum = 0;
            int d = nbins - 1;
            for (; d > 0; d--) {
                if (cum + (int)h[d] >= k) break;
                cum += (int)h[d];
            }
            s_k = k - cum;                       // remaining rank inside chosen digit
            s_prefix = pre | ((unsigned int)d << shift);
        }
        __syncthreads();
    }

    const unsigned int thr = s_prefix;   // exact K_TOK-th largest key
    const int m = s_k;                   // # of threshold-equal elements to include

    for (int i = threadIdx.x; i < N_NEU; i += blockDim.x) {
        unsigned int u = fkey(row[i]);
        if (u > thr) {
            atomicAdd(&g_counts[i], 1);
        } else if (u == thr) {
            int p = atomicAdd(&s_eq_n, 1);
            if (p < 64) s_eq_idx[p] = i;
        }
    }
    __syncthreads();

    if (threadIdx.x == 0) {
        int n = s_eq_n; if (n > 64) n = 64;
        // tiny insertion sort ascending (n is almost always 1, rarely 2)
        for (int a = 1; a < n; a++) {
            int v = s_eq_idx[a]; int b = a - 1;
            while (b >= 0 && s_eq_idx[b] > v) { s_eq_idx[b + 1] = s_eq_idx[b]; b--; }
            s_eq_idx[b + 1] = v;
        }
        int take = m; if (take > n) take = n;
        for (int j = 0; j < take; j++) atomicAdd(&g_counts[s_eq_idx[j]], 1);
    }
}

// -------- histogram of counts --------
__global__ void hist_kernel() {
    int n = blockIdx.x * blockDim.x + threadIdx.x;
    if (n < N_NEU) atomicAdd(&g_hist[g_counts[n]], 1);
}

// -------- bucket start offsets, descending count order --------
__global__ void offsets_kernel() {
    int cum = 0;
    for (int c = 2048; c >= 0; c--) {
        g_off[c] = cum;         // # neurons with count > c
        cum += g_hist[c];
    }
}

// -------- stable emit: core_idx sorted by (count desc, index asc) — exact jax top_k order --------
__global__ void emit_kernel() {
    int c = blockIdx.x * blockDim.x + threadIdx.x;
    if (c > 2048) return;
    int cnt = g_hist[c];
    if (cnt == 0) return;
    int pos = g_off[c];
    if (pos >= N_CORE) return;
    int emitted = 0;
    for (int n = 0; n < N_NEU; n++) {
        if (g_counts[n] == c) {
            g_core_idx[pos++] = n;
            emitted++;
            if (pos >= N_CORE || emitted >= cnt) break;
        }
    }
}

// -------- filtered_W gather: block per output row, stage row in smem --------
__global__ void gather_kernel(const float* __restrict__ W, float* __restrict__ out2) {
    __shared__ float rowbuf[N_NEU];
    const int d = blockIdx.x;
    const float* wr = W + (size_t)d * N_NEU;
    for (int i = threadIdx.x; i < N_NEU / 4; i += blockDim.x)
        ((float4*)rowbuf)[i] = ((const float4*)wr)[i];
    __syncthreads();
    float* o = out2 + (size_t)d * N_CORE;
    for (int j = threadIdx.x; j < N_CORE; j += blockDim.x)
        o[j] = rowbuf[g_core_idx[j]];
}

// -------- fp32 SIMT GEMM: C[t,d] = sum_n X[t,n] * W[d,n] --------
// 128x128 block tile, BK=32, 256 threads, 8x8 per-thread micro-tile.
#define BM 128
#define BN 128
#define BK 32

__global__ __launch_bounds__(256, 2)
void gemm_kernel(const float* __restrict__ X, const float* __restrict__ W,
                 float* __restrict__ C) {
    __shared__ float xs[BK][BM + 4];
    __shared__ float ws[BK][BN + 4];

    const int bt = blockIdx.y * BM;   // token base
    const int bd = blockIdx.x * BN;   // d base
    const int tid = threadIdx.x;
    const int tx = tid & 15;
    const int ty = tid >> 4;

    float acc[8][8];
    #pragma unroll
    for (int i = 0; i < 8; i++)
        #pragma unroll
        for (int j = 0; j < 8; j++) acc[i][j] = 0.0f;

    for (int k0 = 0; k0 < N_NEU; k0 += BK) {
        // load X tile [128 rows][32 k] and W tile, transposed into smem
        #pragma unroll
        for (int r = 0; r < 4; r++) {
            int q   = r * 256 + tid;
            int row = q >> 3;
            int c4  = (q & 7) << 2;
            float4 vx = *(const float4*)(X + (size_t)(bt + row) * N_NEU + k0 + c4);
            xs[c4 + 0][row] = vx.x; xs[c4 + 1][row] = vx.y;
            xs[c4 + 2][row] = vx.z; xs[c4 + 3][row] = vx.w;
            float4 vw = *(const float4*)(W + (size_t)(bd + row) * N_NEU + k0 + c4);
            ws[c4 + 0][row] = vw.x; ws[c4 + 1][row] = vw.y;
            ws[c4 + 2][row] = vw.z; ws[c4 + 3][row] = vw.w;
        }
        __syncthreads();

        #pragma unroll
        for (int kk = 0; kk < BK; kk++) {
            float a[8], b[8];
            float4 a0 = *(const float4*)&xs[kk][ty * 4];
            float4 a1 = *(const float4*)&xs[kk][64 + ty * 4];
            float4 b0 = *(const float4*)&ws[kk][tx * 4];
            float4 b1 = *(const float4*)&ws[kk][64 + tx * 4];
            a[0]=a0.x; a[1]=a0.y; a[2]=a0.z; a[3]=a0.w;
            a[4]=a1.x; a[5]=a1.y; a[6]=a1.z; a[7]=a1.w;
            b[0]=b0.x; b[1]=b0.y; b[2]=b0.z; b[3]=b0.w;
            b[4]=b1.x; b[5]=b1.y; b[6]=b1.z; b[7]=b1.w;
            #pragma unroll
            for (int i = 0; i < 8; i++)
                #pragma unroll
                for (int j = 0; j < 8; j++)
                    acc[i][j] = fmaf(a[i], b[j], acc[i][j]);
        }
        __syncthreads();
    }

    // epilogue
    #pragma unroll
    for (int i = 0; i < 8; i++) {
        int row = bt + ((i < 4) ? (ty * 4 + i) : (64 + ty * 4 + (i - 4)));
        float4 v0 = make_float4(acc[i][0], acc[i][1], acc[i][2], acc[i][3]);
        float4 v1 = make_float4(acc[i][4], acc[i][5], acc[i][6], acc[i][7]);
        *(float4*)(C + (size_t)row * D_OUT + bd + tx * 4)      = v0;
        *(float4*)(C + (size_t)row * D_OUT + bd + 64 + tx * 4) = v1;
    }
}

extern "C" void kernel_launch(void* const* d_in, const int* in_sizes, int n_in,
                              void* d_out, int out_size) {
    const float* X = (const float*)d_in[0];   // (1, 2048, 11008) f32
    const float* W = (const float*)d_in[1];   // (4096, 11008) f32
    float* out = (float*)d_out;               // [true_value | filtered_W]

    (void)in_sizes; (void)n_in; (void)out_size;

    // selection pipeline
    zero_kernel<<<43, 256>>>();                       // 43*256 = 11008 covers both arrays
    topk_count_kernel<<<T_TOK, 256>>>(X);
    hist_kernel<<<43, 256>>>();
    offsets_kernel<<<1, 1>>>();
    emit_kernel<<<9, 256>>>();

    // GEMM -> true_value
    dim3 ggrid(D_OUT / BN, T_TOK / BM);               // (32, 16)
    gemm_kernel<<<ggrid, 256>>>(X, W, out);

    // filtered_W gather
    gather_kernel<<<D_OUT, 256>>>(W, out + (size_t)T_TOK * D_OUT);
}

// round 2
// speedup vs baseline: 1.8846x; 1.8846x over previous
#include <cuda_runtime.h>
#include <cuda_bf16.h>
#include <cstdint>

// Problem constants
#define T_TOK  2048      // tokens
#define N_NEU  11008     // neurons (K dim of GEMM, columns of weight)
#define D_OUT  4096      // output dim (rows of weight)
#define K_TOK  2201      // int(11008 * 0.2)
#define N_CORE 4403      // int(11008 * 0.4)

// -------- device scratch (no allocations allowed) --------
__device__ int g_counts[N_NEU];
__device__ int g_hist[2049];     // counts take values 0..2048
__device__ int g_off[2049];
__device__ int g_cursor[2049];
__device__ int g_scratch[N_NEU]; // bucket-partitioned neuron ids; [0..N_CORE) == core_idx

// order-preserving float -> uint map (ascending)
__device__ __forceinline__ unsigned int fkey(float f) {
    unsigned int u = __float_as_uint(f);
    return (u & 0x80000000u) ? ~u : (u | 0x80000000u);
}

// -------- reset scratch each launch (graph-replay safe) --------
__global__ void zero_kernel() {
    int i = blockIdx.x * blockDim.x + threadIdx.x;
    if (i < N_NEU) g_counts[i] = 0;
    if (i < 2049) { g_hist[i] = 0; g_cursor[i] = 0; }
}

// -------- per-token exact top-K threshold (3-level MSB radix select) + vote count --------
// Replicates jax.lax.top_k: exactly K_TOK per token, ties at threshold -> lowest index first.
__global__ void topk_count_kernel(const float* __restrict__ X) {
    __shared__ unsigned int h[2048];
    __shared__ unsigned int s_prefix;
    __shared__ int s_k;
    __shared__ int s_eq_n;
    __shared__ int s_eq_idx[64];

    const int t = blockIdx.x;
    const float* row = X + (size_t)t * N_NEU;

    if (threadIdx.x == 0) { s_prefix = 0u; s_k = K_TOK; s_eq_n = 0; }

    #pragma unroll
    for (int p = 0; p < 3; p++) {
        const int shift = (p == 0) ? 21 : (p == 1) ? 10 : 0;
        const int nbins = (p == 2) ? 1024 : 2048;
        const unsigned int himask =
            (p == 0) ? 0u : ((p == 1) ? (0xFFFFFFFFu << 21) : (0xFFFFFFFFu << 10));

        for (int i = threadIdx.x; i < nbins; i += blockDim.x) h[i] = 0u;
        __syncthreads();

        const unsigned int pre = s_prefix;
        for (int i = threadIdx.x; i < N_NEU; i += blockDim.x) {
            unsigned int u = fkey(row[i]);
            if ((u & himask) == pre)
                atomicAdd(&h[(u >> shift) & (unsigned)(nbins - 1)], 1u);
        }
        __syncthreads();

        if (threadIdx.x == 0) {
            int k = s_k;
            int cum = 0;
            int d = nbins - 1;
            for (; d > 0; d--) {
                if (cum + (int)h[d] >= k) break;
                cum += (int)h[d];
            }
            s_k = k - cum;
            s_prefix = pre | ((unsigned int)d << shift);
        }
        __syncthreads();
    }

    const unsigned int thr = s_prefix;
    const int m = s_k;

    for (int i = threadIdx.x; i < N_NEU; i += blockDim.x) {
        unsigned int u = fkey(row[i]);
        if (u > thr) {
            atomicAdd(&g_counts[i], 1);
        } else if (u == thr) {
            int p = atomicAdd(&s_eq_n, 1);
            if (p < 64) s_eq_idx[p] = i;
        }
    }
    __syncthreads();

    if (threadIdx.x == 0) {
        int n = s_eq_n; if (n > 64) n = 64;
        for (int a = 1; a < n; a++) {
            int v = s_eq_idx[a]; int b = a - 1;
            while (b >= 0 && s_eq_idx[b] > v) { s_eq_idx[b + 1] = s_eq_idx[b]; b--; }
            s_eq_idx[b + 1] = v;
        }
        int take = m; if (take > n) take = n;
        for (int j = 0; j < take; j++) atomicAdd(&g_counts[s_eq_idx[j]], 1);
    }
}

// -------- histogram of counts --------
__global__ void hist_kernel() {
    int n = blockIdx.x * blockDim.x + threadIdx.x;
    if (n < N_NEU) atomicAdd(&g_hist[g_counts[n]], 1);
}

// -------- bucket start offsets (descending count order), smem-staged scan --------
__global__ void scan_kernel() {
    __shared__ int sh[2049];
    for (int i = threadIdx.x; i < 2049; i += blockDim.x) sh[i] = g_hist[i];
    __syncthreads();
    if (threadIdx.x == 0) {
        int cum = 0;
        for (int c = 2048; c >= 0; c--) { g_off[c] = cum; cum += sh[c]; }
    }
}

// -------- scatter neurons into their count-bucket segment (order unstable) --------
__global__ void fill_kernel() {
    int n = blockIdx.x * blockDim.x + threadIdx.x;
    if (n < N_NEU) {
        int c = g_counts[n];
        int pos = g_off[c] + atomicAdd(&g_cursor[c], 1);
        g_scratch[pos] = n;
    }
}

// -------- sort each bucket ascending by index (stable (count desc, idx asc) overall) ----
__global__ void sort_kernel() {
    const int c = blockIdx.x;
    const int beg = g_off[c];
    const int cnt = g_hist[c];
    if (cnt <= 1) return;
    if (beg >= N_CORE) return;  // bucket entirely outside core set: order irrelevant

    __shared__ int buf[2048];
    if (cnt <= 2048) {
        for (int i = threadIdx.x; i < cnt; i += blockDim.x) buf[i] = g_scratch[beg + i];
        __syncthreads();
        for (int ph = 0; ph < cnt; ph++) {
            int st = ph & 1;
            for (int i = threadIdx.x; st + 2 * i + 1 < cnt; i += blockDim.x) {
                int a = st + 2 * i;
                int u = buf[a], v = buf[a + 1];
                if (u > v) { buf[a] = v; buf[a + 1] = u; }
            }
            __syncthreads();
        }
        for (int i = threadIdx.x; i < cnt; i += blockDim.x) g_scratch[beg + i] = buf[i];
    } else {
        if (threadIdx.x == 0) {  // paranoia fallback, never expected
            for (int a = beg + 1; a < beg + cnt; a++) {
                int v = g_scratch[a]; int b = a - 1;
                while (b >= beg && g_scratch[b] > v) { g_scratch[b + 1] = g_scratch[b]; b--; }
                g_scratch[b + 1] = v;
            }
        }
    }
}

// -------- filtered_W gather: block per output row, stage row in smem --------
__global__ void gather_kernel(const float* __restrict__ W, float* __restrict__ out2) {
    __shared__ float rowbuf[N_NEU];
    const int d = blockIdx.x;
    const float* wr = W + (size_t)d * N_NEU;
    for (int i = threadIdx.x; i < N_NEU / 4; i += blockDim.x)
        ((float4*)rowbuf)[i] = ((const float4*)wr)[i];
    __syncthreads();
    float* o = out2 + (size_t)d * N_CORE;
    for (int j = threadIdx.x; j < N_CORE; j += blockDim.x)
        o[j] = rowbuf[g_scratch[j]];
}

// ==================== bf16x3 split GEMM on tensor pipe ====================
// C[t,d] = sum_n X[t,n] * W[d,n], fp32 in/out, computed as
//   (Xhi+Xlo)(Whi+Wlo) ~= Xhi*Whi + Xhi*Wlo + Xlo*Whi   (fp32 accumulate)
// 128x128 CTA tile, BK=32, 8 warps (2M x 4N), warp tile 64x32, mma.m16n8k16.

#define GBM 128
#define GBN 128
#define GBK 32
#define LDA 40   // bf16 elems per smem row (32 + 8 pad) -> 80B row stride, conflict-free frags

#define MMA_BF16(d, a, b)                                                     \
    asm volatile(                                                             \
        "mma.sync.aligned.m16n8k16.row.col.f32.bf16.bf16.f32 "                \
        "{%0,%1,%2,%3}, {%4,%5,%6,%7}, {%8,%9}, {%0,%1,%2,%3};"               \
        : "+f"(d[0]), "+f"(d[1]), "+f"(d[2]), "+f"(d[3])                      \
        : "r"(a[0]), "r"(a[1]), "r"(a[2]), "r"(a[3]), "r"(b[0]), "r"(b[1]))

__global__ __launch_bounds__(256, 1)
void gemm_bf16x3_kernel(const float* __restrict__ X, const float* __restrict__ W,
                        float* __restrict__ C) {
    __shared__ __nv_bfloat16 Ah[GBM][LDA], Al[GBM][LDA];
    __shared__ __nv_bfloat16 Bh[GBN][LDA], Bl[GBN][LDA];

    const int tid  = threadIdx.x;
    const int lane = tid & 31;
    const int wid  = tid >> 5;
    const int wm   = (wid & 1) * 64;    // warp M offset
    const int wn   = (wid >> 1) * 32;   // warp N offset
    const int g    = lane >> 2;         // group id 0..7
    const int tig  = lane & 3;          // thread in group

    const int bt = blockIdx.y * GBM;
    const int bd = blockIdx.x * GBN;

    float acc[4][4][4];
    #pragma unroll
    for (int i = 0; i < 4; i++)
        #pragma unroll
        for (int j = 0; j < 4; j++)
            #pragma unroll
            for (int r = 0; r < 4; r++) acc[i][j][r] = 0.0f;

    float4 xr[4], wr[4];

    // prefetch stage 0
    #pragma unroll
    for (int i = 0; i < 4; i++) {
        int q = i * 256 + tid;
        int r = q >> 3;
        int c = (q & 7) << 2;
        xr[i] = *(const float4*)(X + (size_t)(bt + r) * N_NEU + c);
        wr[i] = *(const float4*)(W + (size_t)(bd + r) * N_NEU + c);
    }

    const int NIT = N_NEU / GBK;  // 344
    for (int it = 0; it < NIT; it++) {
        // convert + store current stage to smem
        #pragma unroll
        for (int i = 0; i < 4; i++) {
            int q = i * 256 + tid;
            int r = q >> 3;
            int c = (q & 7) << 2;
            float vx[4] = {xr[i].x, xr[i].y, xr[i].z, xr[i].w};
            float vw[4] = {wr[i].x, wr[i].y, wr[i].z, wr[i].w};
            #pragma unroll
            for (int j = 0; j < 4; j++) {
                __nv_bfloat16 xh = __float2bfloat16_rn(vx[j]);
                __nv_bfloat16 xl = __float2bfloat16_rn(vx[j] - __bfloat162float(xh));
                __nv_bfloat16 wh = __float2bfloat16_rn(vw[j]);
                __nv_bfloat16 wl = __float2bfloat16_rn(vw[j] - __bfloat162float(wh));
                Ah[r][c + j] = xh; Al[r][c + j] = xl;
                Bh[r][c + j] = wh; Bl[r][c + j] = wl;
            }
        }
        __syncthreads();

        // prefetch next stage (hidden behind compute)
        if (it + 1 < NIT) {
            int k0 = (it + 1) * GBK;
            #pragma unroll
            for (int i = 0; i < 4; i++) {
                int q = i * 256 + tid;
                int r = q >> 3;
                int c = (q & 7) << 2;
                xr[i] = *(const float4*)(X + (size_t)(bt + r) * N_NEU + k0 + c);
                wr[i] = *(const float4*)(W + (size_t)(bd + r) * N_NEU + k0 + c);
            }
        }

        // compute two k16 steps
        #pragma unroll
        for (int ks = 0; ks < 2; ks++) {
            const int ko = ks * 16;
            uint32_t ah[4][4], al[4][4], bh[4][2], bl[4][2];
            #pragma unroll
            for (int mt = 0; mt < 4; mt++) {
                int r0 = wm + mt * 16;
                ah[mt][0] = *(const uint32_t*)&Ah[r0 + g    ][ko + tig * 2    ];
                ah[mt][1] = *(const uint32_t*)&Ah[r0 + g + 8][ko + tig * 2    ];
                ah[mt][2] = *(const uint32_t*)&Ah[r0 + g    ][ko + tig * 2 + 8];
                ah[mt][3] = *(const uint32_t*)&Ah[r0 + g + 8][ko + tig * 2 + 8];
                al[mt][0] = *(const uint32_t*)&Al[r0 + g    ][ko + tig * 2    ];
                al[mt][1] = *(const uint32_t*)&Al[r0 + g + 8][ko + tig * 2    ];
                al[mt][2] = *(const uint32_t*)&Al[r0 + g    ][ko + tig * 2 + 8];
                al[mt][3] = *(const uint32_t*)&Al[r0 + g + 8][ko + tig * 2 + 8];
            }
            #pragma unroll
            for (int nt = 0; nt < 4; nt++) {
                int n0 = wn + nt * 8;
                bh[nt][0] = *(const uint32_t*)&Bh[n0 + g][ko + tig * 2    ];
                bh[nt][1] = *(const uint32_t*)&Bh[n0 + g][ko + tig * 2 + 8];
                bl[nt][0] = *(const uint32_t*)&Bl[n0 + g][ko + tig * 2    ];
                bl[nt][1] = *(const uint32_t*)&Bl[n0 + g][ko + tig * 2 + 8];
            }
            #pragma unroll
            for (int mt = 0; mt < 4; mt++)
                #pragma unroll
                for (int nt = 0; nt < 4; nt++) MMA_BF16(acc[mt][nt], ah[mt], bh[nt]);
            #pragma unroll
            for (int mt = 0; mt < 4; mt++)
                #pragma unroll
                for (int nt = 0; nt < 4; nt++) MMA_BF16(acc[mt][nt], ah[mt], bl[nt]);
            #pragma unroll
            for (int mt = 0; mt < 4; mt++)
                #pragma unroll
                for (int nt = 0; nt < 4; nt++) MMA_BF16(acc[mt][nt], al[mt], bh[nt]);
        }
        __syncthreads();
    }

    // epilogue
    #pragma unroll
    for (int mt = 0; mt < 4; mt++) {
        #pragma unroll
        for (int nt = 0; nt < 4; nt++) {
            int t0 = bt + wm + mt * 16 + g;
            int d0 = bd + wn + nt * 8 + tig * 2;
            float2 v0 = make_float2(acc[mt][nt][0], acc[mt][nt][1]);
            float2 v1 = make_float2(acc[mt][nt][2], acc[mt][nt][3]);
            *(float2*)(C + (size_t)t0 * D_OUT + d0)       = v0;
            *(float2*)(C + (size_t)(t0 + 8) * D_OUT + d0) = v1;
        }
    }
}

extern "C" void kernel_launch(void* const* d_in, const int* in_sizes, int n_in,
                              void* d_out, int out_size) {
    const float* X = (const float*)d_in[0];   // (1, 2048, 11008) f32
    const float* W = (const float*)d_in[1];   // (4096, 11008) f32
    float* out = (float*)d_out;               // [true_value | filtered_W]

    (void)in_sizes; (void)n_in; (void)out_size;

    // selection pipeline
    zero_kernel<<<43, 256>>>();
    topk_count_kernel<<<T_TOK, 256>>>(X);
    hist_kernel<<<43, 256>>>();
    scan_kernel<<<1, 256>>>();
    fill_kernel<<<43, 256>>>();
    sort_kernel<<<2049, 128>>>();

    // GEMM -> true_value (tensor pipe, bf16x3 split)
    dim3 ggrid(D_OUT / GBN, T_TOK / GBM);     // (32, 16)
    gemm_bf16x3_kernel<<<ggrid, 256>>>(X, W, out);

    // filtered_W gather
    gather_kernel<<<D_OUT, 256>>>(W, out + (size_t)T_TOK * D_OUT);
}

// round 4
// speedup vs baseline: 2.3609x; 1.2527x over previous
#include <cuda_runtime.h>
#include <cuda_bf16.h>
#include <cstdint>

// Problem constants
#define T_TOK  2048
#define N_NEU  11008
#define D_OUT  4096
#define K_TOK  2201      // int(11008 * 0.2)
#define N_CORE 4403      // int(11008 * 0.4)

// -------- device scratch (static, no runtime allocation) --------
__device__ int g_counts[N_NEU];
__device__ int g_hist[2049];
__device__ int g_off[2049];
__device__ int g_cursor[2049];
__device__ int g_scratch[N_NEU];

// pre-converted bf16 split operands (hi + lo)
__device__ __nv_bfloat16 g_Xhi[(size_t)T_TOK * N_NEU];
__device__ __nv_bfloat16 g_Xlo[(size_t)T_TOK * N_NEU];
__device__ __nv_bfloat16 g_Whi[(size_t)D_OUT * N_NEU];
__device__ __nv_bfloat16 g_Wlo[(size_t)D_OUT * N_NEU];

// ---------------- helpers ----------------
__device__ __forceinline__ uint32_t smem_u32(const void* p) {
    uint32_t a;
    asm("{ .reg .u64 t; cvta.to.shared.u64 t, %1; cvt.u32.u64 %0, t; }" : "=r"(a) : "l"(p));
    return a;
}
__device__ __forceinline__ void cp_async16(uint32_t saddr, const void* gaddr) {
    asm volatile("cp.async.cg.shared.global [%0], [%1], 16;" :: "r"(saddr), "l"(gaddr));
}
__device__ __forceinline__ void cp_commit() { asm volatile("cp.async.commit_group;"); }
__device__ __forceinline__ void cp_wait1()  { asm volatile("cp.async.wait_group 1;"); }

__device__ __forceinline__ void ldsm_x4(uint32_t& r0, uint32_t& r1, uint32_t& r2, uint32_t& r3,
                                        uint32_t addr) {
    asm volatile("ldmatrix.sync.aligned.m8n8.x4.shared.b16 {%0,%1,%2,%3}, [%4];"
                 : "=r"(r0), "=r"(r1), "=r"(r2), "=r"(r3) : "r"(addr));
}

#define MMA_BF16(d, a, b)                                                     \
    asm volatile(                                                             \
        "mma.sync.aligned.m16n8k16.row.col.f32.bf16.bf16.f32 "                \
        "{%0,%1,%2,%3}, {%4,%5,%6,%7}, {%8,%9}, {%0,%1,%2,%3};"               \
        : "+f"(d[0]), "+f"(d[1]), "+f"(d[2]), "+f"(d[3])                      \
        : "r"(a[0]), "r"(a[1]), "r"(a[2]), "r"(a[3]), "r"(b[0]), "r"(b[1]))

// order-preserving float -> uint map (ascending)
__device__ __forceinline__ unsigned int fkey(float f) {
    unsigned int u = __float_as_uint(f);
    return (u & 0x80000000u) ? ~u : (u | 0x80000000u);
}

// -------- reset scratch each launch --------
__global__ void zero_kernel() {
    int i = blockIdx.x * blockDim.x + threadIdx.x;
    if (i < N_NEU) g_counts[i] = 0;
    if (i < 2049) { g_hist[i] = 0; g_cursor[i] = 0; }
}

// -------- pre-convert f32 -> bf16 hi/lo split --------
__global__ void convert_kernel(const float* __restrict__ src,
                               __nv_bfloat16* __restrict__ hi,
                               __nv_bfloat16* __restrict__ lo, int n4) {
    int i = blockIdx.x * blockDim.x + threadIdx.x;
    if (i >= n4) return;
    float4 v = ((const float4*)src)[i];
    float a[4] = {v.x, v.y, v.z, v.w};
    __nv_bfloat16 h[4], l[4];
    #pragma unroll
    for (int j = 0; j < 4; j++) {
        h[j] = __float2bfloat16_rn(a[j]);
        l[j] = __float2bfloat16_rn(a[j] - __bfloat162float(h[j]));
    }
    ((__nv_bfloat162*)hi)[2 * i]     = __nv_bfloat162(h[0], h[1]);
    ((__nv_bfloat162*)hi)[2 * i + 1] = __nv_bfloat162(h[2], h[3]);
    ((__nv_bfloat162*)lo)[2 * i]     = __nv_bfloat162(l[0], l[1]);
    ((__nv_bfloat162*)lo)[2 * i + 1] = __nv_bfloat162(l[2], l[3]);
}

// -------- per-token exact top-K (3-level MSB radix select) + vote count --------
__global__ void topk_count_kernel(const float* __restrict__ X) {
    __shared__ unsigned int h[2048];
    __shared__ unsigned int s_prefix;
    __shared__ int s_k;
    __shared__ int s_eq_n;
    __shared__ int s_eq_idx[64];

    const int t = blockIdx.x;
    const float* row = X + (size_t)t * N_NEU;

    if (threadIdx.x == 0) { s_prefix = 0u; s_k = K_TOK; s_eq_n = 0; }

    #pragma unroll
    for (int p = 0; p < 3; p++) {
        const int shift = (p == 0) ? 21 : (p == 1) ? 10 : 0;
        const int nbins = (p == 2) ? 1024 : 2048;
        const unsigned int himask =
            (p == 0) ? 0u : ((p == 1) ? (0xFFFFFFFFu << 21) : (0xFFFFFFFFu << 10));

        for (int i = threadIdx.x; i < nbins; i += blockDim.x) h[i] = 0u;
        __syncthreads();

        const unsigned int pre = s_prefix;
        for (int i = threadIdx.x; i < N_NEU; i += blockDim.x) {
            unsigned int u = fkey(row[i]);
            if ((u & himask) == pre)
                atomicAdd(&h[(u >> shift) & (unsigned)(nbins - 1)], 1u);
        }
        __syncthreads();

        if (threadIdx.x == 0) {
            int k = s_k, cum = 0, d = nbins - 1;
            for (; d > 0; d--) {
                if (cum + (int)h[d] >= k) break;
                cum += (int)h[d];
            }
            s_k = k - cum;
            s_prefix = pre | ((unsigned int)d << shift);
        }
        __syncthreads();
    }

    const unsigned int thr = s_prefix;
    const int m = s_k;

    for (int i = threadIdx.x; i < N_NEU; i += blockDim.x) {
        unsigned int u = fkey(row[i]);
        if (u > thr) {
            atomicAdd(&g_counts[i], 1);
        } else if (u == thr) {
            int p = atomicAdd(&s_eq_n, 1);
            if (p < 64) s_eq_idx[p] = i;
        }
    }
    __syncthreads();

    if (threadIdx.x == 0) {
        int n = s_eq_n; if (n > 64) n = 64;
        for (int a = 1; a < n; a++) {
            int v = s_eq_idx[a]; int b = a - 1;
            while (b >= 0 && s_eq_idx[b] > v) { s_eq_idx[b + 1] = s_eq_idx[b]; b--; }
            s_eq_idx[b + 1] = v;
        }
        int take = m; if (take > n) take = n;
        for (int j = 0; j < take; j++) atomicAdd(&g_counts[s_eq_idx[j]], 1);
    }
}

__global__ void hist_kernel() {
    int n = blockIdx.x * blockDim.x + threadIdx.x;
    if (n < N_NEU) atomicAdd(&g_hist[g_counts[n]], 1);
}

__global__ void scan_kernel() {
    __shared__ int sh[2049];
    for (int i = threadIdx.x; i < 2049; i += blockDim.x) sh[i] = g_hist[i];
    __syncthreads();
    if (threadIdx.x == 0) {
        int cum = 0;
        for (int c = 2048; c >= 0; c--) { g_off[c] = cum; cum += sh[c]; }
    }
}

__global__ void fill_kernel() {
    int n = blockIdx.x * blockDim.x + threadIdx.x;
    if (n < N_NEU) {
        int c = g_counts[n];
        int pos = g_off[c] + atomicAdd(&g_cursor[c], 1);
        g_scratch[pos] = n;
    }
}

__global__ void sort_kernel() {
    const int c = blockIdx.x;
    const int beg = g_off[c];
    const int cnt = g_hist[c];
    if (cnt <= 1) return;
    if (beg >= N_CORE) return;

    __shared__ int buf[2048];
    if (cnt <= 2048) {
        for (int i = threadIdx.x; i < cnt; i += blockDim.x) buf[i] = g_scratch[beg + i];
        __syncthreads();
        for (int ph = 0; ph < cnt; ph++) {
            int st = ph & 1;
            for (int i = threadIdx.x; st + 2 * i + 1 < cnt; i += blockDim.x) {
                int a = st + 2 * i;
                int u = buf[a], v = buf[a + 1];
                if (u > v) { buf[a] = v; buf[a + 1] = u; }
            }
            __syncthreads();
        }
        for (int i = threadIdx.x; i < cnt; i += blockDim.x) g_scratch[beg + i] = buf[i];
    } else {
        if (threadIdx.x == 0) {
            for (int a = beg + 1; a < beg + cnt; a++) {
                int v = g_scratch[a]; int b = a - 1;
                while (b >= beg && g_scratch[b] > v) { g_scratch[b + 1] = g_scratch[b]; b--; }
                g_scratch[b + 1] = v;
            }
        }
    }
}

__global__ void gather_kernel(const float* __restrict__ W, float* __restrict__ out2) {
    __shared__ float rowbuf[N_NEU];
    const int d = blockIdx.x;
    const float* wr = W + (size_t)d * N_NEU;
    for (int i = threadIdx.x; i < N_NEU / 4; i += blockDim.x)
        ((float4*)rowbuf)[i] = ((const float4*)wr)[i];
    __syncthreads();
    float* o = out2 + (size_t)d * N_CORE;
    for (int j = threadIdx.x; j < N_CORE; j += blockDim.x)
        o[j] = rowbuf[g_scratch[j]];
}

// ==================== mma.sync bf16x3 GEMM, pre-converted, cp.async + ldmatrix ========
// 128x128 CTA tile, BK=32, 8 warps (2M x 4N), warp tile 64x32.
// 3-stage cp.async pipeline; 24 LDSM.x4 + 96 HMMA per warp per k-tile.

#define GBM 128
#define GBN 128
#define GBK 32
#define ROWB 80                      // bytes per smem row: 64B data + 16B pad
#define ARR  (128 * ROWB)            // 10240 B per operand array
#define STG  (4 * ARR)               // 40960 B per stage (Ah, Al, Bh, Bl)
#define NSTG 3
#define GEMM_SMEM (NSTG * STG)       // 122880 B
#define OFF_AH 0
#define OFF_AL ARR
#define OFF_BH (2 * ARR)
#define OFF_BL (3 * ARR)
#define NIT (N_NEU / GBK)            // 344

__global__ __launch_bounds__(256, 1)
void gemm_mma_kernel(float* __restrict__ C) {
    extern __shared__ char smem[];
    const uint32_t sb0 = smem_u32(smem);

    const int tid  = threadIdx.x;
    const int lane = tid & 31;
    const int wid  = tid >> 5;
    const int wm   = (wid & 1) * 64;
    const int wn   = (wid >> 1) * 32;

    const int bt = blockIdx.y * GBM;
    const int bd = blockIdx.x * GBN;

    const __nv_bfloat16* Xh = g_Xhi;
    const __nv_bfloat16* Xl = g_Xlo;
    const __nv_bfloat16* Wh = g_Whi;
    const __nv_bfloat16* Wl = g_Wlo;

    // per-thread cp.async mapping: 2 chunks per operand array (512 chunks / 256 thr)
    // chunk q: row r = q>>2, chunk c = q&3 ; smem off = r*80 + c*16 ; gmem col = c*8
    const int q0 = tid, q1 = 256 + tid;
    const int r0 = q0 >> 2, c0 = q0 & 3;
    const int r1 = q1 >> 2, c1 = q1 & 3;

    auto load_stage = [&](int it, int s) {
        const uint32_t sb = sb0 + s * STG;
        const int k0 = it * GBK;
        const size_t gxa = (size_t)(bt + r0) * N_NEU + k0 + c0 * 8;
        const size_t gxb = (size_t)(bt + r1) * N_NEU + k0 + c1 * 8;
        const size_t gwa = (size_t)(bd + r0) * N_NEU + k0 + c0 * 8;
        const size_t gwb = (size_t)(bd + r1) * N_NEU + k0 + c1 * 8;
        const uint32_t o0 = (uint32_t)(r0 * ROWB + c0 * 16);
        const uint32_t o1 = (uint32_t)(r1 * ROWB + c1 * 16);
        cp_async16(sb + OFF_AH + o0, Xh + gxa);
        cp_async16(sb + OFF_AH + o1, Xh + gxb);
        cp_async16(sb + OFF_AL + o0, Xl + gxa);
        cp_async16(sb + OFF_AL + o1, Xl + gxb);
        cp_async16(sb + OFF_BH + o0, Wh + gwa);
        cp_async16(sb + OFF_BH + o1, Wh + gwb);
        cp_async16(sb + OFF_BL + o0, Wl + gwa);
        cp_async16(sb + OFF_BL + o1, Wl + gwb);
    };

    float acc[4][4][4];
    #pragma unroll
    for (int i = 0; i < 4; i++)
        #pragma unroll
        for (int j = 0; j < 4; j++)
            #pragma unroll
            for (int r = 0; r < 4; r++) acc[i][j][r] = 0.0f;

    // ldmatrix per-lane address pieces
    const int mi = lane >> 3, ri = lane & 7;
    // A: row = wm + mt*16 + (mi&1)*8 + ri ; colbytes = ks*32 + (mi>>1)*16
    const uint32_t a_row_off = (uint32_t)((wm + (mi & 1) * 8 + ri) * ROWB + (mi >> 1) * 16);
    // B: row = wn + ntp*16 + (mi>>1)*8 + ri ; colbytes = ks*32 + (mi&1)*16
    const uint32_t b_row_off = (uint32_t)((wn + (mi >> 1) * 8 + ri) * ROWB + (mi & 1) * 16);

    // prologue: stages 0,1
    load_stage(0, 0); cp_commit();
    load_stage(1, 1); cp_commit();

    for (int it = 0; it < NIT; it++) {
        cp_wait1();                 // stage `it` landed (stage it+1 may be in flight)
        __syncthreads();            // data visible + all warps done with stage it-1

        // refill: stage it+2 goes into buffer (it+2)%3 == buffer of stage it-1 (freed)
        if (it + 2 < NIT) load_stage(it + 2, (it + 2) % NSTG);
        cp_commit();                // always commit (possibly empty) to keep group count exact

        const uint32_t sb = sb0 + (it % NSTG) * STG;
        const uint32_t aAh = sb + OFF_AH + a_row_off;
        const uint32_t aAl = sb + OFF_AL + a_row_off;
        const uint32_t aBh = sb + OFF_BH + b_row_off;
        const uint32_t aBl = sb + OFF_BL + b_row_off;

        #pragma unroll
        for (int ks = 0; ks < 2; ks++) {
            const uint32_t ko = ks * 32;
            uint32_t ah[4][4], al[4][4], bh[4][2], bl[4][2];
            #pragma unroll
            for (int mt = 0; mt < 4; mt++) {
                ldsm_x4(ah[mt][0], ah[mt][1], ah[mt][2], ah[mt][3],
                        aAh + ko + (uint32_t)(mt * 16 * ROWB));
                ldsm_x4(al[mt][0], al[mt][1], al[mt][2], al[mt][3],
                        aAl + ko + (uint32_t)(mt * 16 * ROWB));
            }
            #pragma unroll
            for (int ntp = 0; ntp < 2; ntp++) {
                ldsm_x4(bh[2 * ntp][0], bh[2 * ntp][1], bh[2 * ntp + 1][0], bh[2 * ntp + 1][1],
                        aBh + ko + (uint32_t)(ntp * 16 * ROWB));
                ldsm_x4(bl[2 * ntp][0], bl[2 * ntp][1], bl[2 * ntp + 1][0], bl[2 * ntp + 1][1],
                        aBl + ko + (uint32_t)(ntp * 16 * ROWB));
            }
            #pragma unroll
            for (int mt = 0; mt < 4; mt++)
                #pragma unroll
                for (int nt = 0; nt < 4; nt++) MMA_BF16(acc[mt][nt], ah[mt], bh[nt]);
            #pragma unroll
            for (int mt = 0; mt < 4; mt++)
                #pragma unroll
                for (int nt = 0; nt < 4; nt++) MMA_BF16(acc[mt][nt], ah[mt], bl[nt]);
            #pragma unroll
            for (int mt = 0; mt < 4; mt++)
                #pragma unroll
                for (int nt = 0; nt < 4; nt++) MMA_BF16(acc[mt][nt], al[mt], bh[nt]);
        }
    }

    // epilogue
    const int g   = lane >> 2;
    const int tig = lane & 3;
    #pragma unroll
    for (int mt = 0; mt < 4; mt++) {
        #pragma unroll
        for (int nt = 0; nt < 4; nt++) {
            int t0 = bt + wm + mt * 16 + g;
            int d0 = bd + wn + nt * 8 + tig * 2;
            float2 v0 = make_float2(acc[mt][nt][0], acc[mt][nt][1]);
            float2 v1 = make_float2(acc[mt][nt][2], acc[mt][nt][3]);
            *(float2*)(C + (size_t)t0 * D_OUT + d0)       = v0;
            *(float2*)(C + (size_t)(t0 + 8) * D_OUT + d0) = v1;
        }
    }
}

extern "C" void kernel_launch(void* const* d_in, const int* in_sizes, int n_in,
                              void* d_out, int out_size) {
    const float* X = (const float*)d_in[0];
    const float* W = (const float*)d_in[1];
    float* out = (float*)d_out;
    (void)in_sizes; (void)n_in; (void)out_size;

    cudaFuncSetAttribute(gemm_mma_kernel, cudaFuncAttributeMaxDynamicSharedMemorySize, GEMM_SMEM);

    // pre-convert operands to bf16 hi/lo
    {
        __nv_bfloat16 *xh, *xl, *wh, *wl;
        cudaGetSymbolAddress((void**)&xh, g_Xhi);
        cudaGetSymbolAddress((void**)&xl, g_Xlo);
        cudaGetSymbolAddress((void**)&wh, g_Whi);
        cudaGetSymbolAddress((void**)&wl, g_Wlo);
        const int nx4 = (T_TOK * N_NEU) / 4;
        const int nw4 = (D_OUT * N_NEU) / 4;
        convert_kernel<<<(nx4 + 255) / 256, 256>>>(X, xh, xl, nx4);
        convert_kernel<<<(nw4 + 255) / 256, 256>>>(W, wh, wl, nw4);
    }

    // selection pipeline
    zero_kernel<<<43, 256>>>();
    topk_count_kernel<<<T_TOK, 256>>>(X);
    hist_kernel<<<43, 256>>>();
    scan_kernel<<<1, 256>>>();
    fill_kernel<<<43, 256>>>();
    sort_kernel<<<2049, 128>>>();

    // GEMM -> true_value
    dim3 ggrid(D_OUT / GBN, T_TOK / GBM);   // (32, 16)
    gemm_mma_kernel<<<ggrid, 256, GEMM_SMEM>>>(out);

    // filtered_W gather
    gather_kernel<<<D_OUT, 256>>>(W, out + (size_t)T_TOK * D_OUT);
}

// round 5
// speedup vs baseline: 2.5907x; 1.0974x over previous
#include <cuda_runtime.h>
#include <cuda_bf16.h>
#include <cstdint>

// Problem constants
#define T_TOK  2048
#define N_NEU  11008
#define D_OUT  4096
#define K_TOK  2201      // int(11008 * 0.2)
#define N_CORE 4403      // int(11008 * 0.4)

// -------- device scratch (static, no runtime allocation) --------
__device__ int g_counts[N_NEU];
__device__ int g_hist[2049];
__device__ int g_off[2049];
__device__ int g_cursor[2049];
__device__ int g_scratch[N_NEU];

// pre-converted bf16 split operands (hi + lo)
__device__ __nv_bfloat16 g_Xhi[(size_t)T_TOK * N_NEU];
__device__ __nv_bfloat16 g_Xlo[(size_t)T_TOK * N_NEU];
__device__ __nv_bfloat16 g_Whi[(size_t)D_OUT * N_NEU];
__device__ __nv_bfloat16 g_Wlo[(size_t)D_OUT * N_NEU];

// ---------------- helpers ----------------
__device__ __forceinline__ uint32_t smem_u32(const void* p) {
    uint32_t a;
    asm("{ .reg .u64 t; cvta.to.shared.u64 t, %1; cvt.u32.u64 %0, t; }" : "=r"(a) : "l"(p));
    return a;
}
__device__ __forceinline__ void cp_async16(uint32_t saddr, const void* gaddr) {
    asm volatile("cp.async.cg.shared.global [%0], [%1], 16;" :: "r"(saddr), "l"(gaddr));
}
__device__ __forceinline__ void cp_commit() { asm volatile("cp.async.commit_group;"); }
__device__ __forceinline__ void cp_wait0()  { asm volatile("cp.async.wait_group 0;"); }

__device__ __forceinline__ void ldsm_x4(uint32_t& r0, uint32_t& r1, uint32_t& r2, uint32_t& r3,
                                        uint32_t addr) {
    asm volatile("ldmatrix.sync.aligned.m8n8.x4.shared.b16 {%0,%1,%2,%3}, [%4];"
                 : "=r"(r0), "=r"(r1), "=r"(r2), "=r"(r3) : "r"(addr));
}

#define MMA_BF16(d, a, b)                                                     \
    asm volatile(                                                             \
        "mma.sync.aligned.m16n8k16.row.col.f32.bf16.bf16.f32 "                \
        "{%0,%1,%2,%3}, {%4,%5,%6,%7}, {%8,%9}, {%0,%1,%2,%3};"               \
        : "+f"(d[0]), "+f"(d[1]), "+f"(d[2]), "+f"(d[3])                      \
        : "r"(a[0]), "r"(a[1]), "r"(a[2]), "r"(a[3]), "r"(b[0]), "r"(b[1]))

// order-preserving float -> uint map (ascending)
__device__ __forceinline__ unsigned int fkey(float f) {
    unsigned int u = __float_as_uint(f);
    return (u & 0x80000000u) ? ~u : (u | 0x80000000u);
}

// -------- reset scratch each launch --------
__global__ void zero_kernel() {
    int i = blockIdx.x * blockDim.x + threadIdx.x;
    if (i < N_NEU) g_counts[i] = 0;
    if (i < 2049) { g_hist[i] = 0; g_cursor[i] = 0; }
}

// -------- pre-convert f32 -> bf16 hi/lo split (W only; X fused into topk) --------
__global__ void convert_kernel(const float* __restrict__ src,
                               __nv_bfloat16* __restrict__ hi,
                               __nv_bfloat16* __restrict__ lo, int n4) {
    int i = blockIdx.x * blockDim.x + threadIdx.x;
    if (i >= n4) return;
    float4 v = ((const float4*)src)[i];
    float a[4] = {v.x, v.y, v.z, v.w};
    __nv_bfloat16 h[4], l[4];
    #pragma unroll
    for (int j = 0; j < 4; j++) {
        h[j] = __float2bfloat16_rn(a[j]);
        l[j] = __float2bfloat16_rn(a[j] - __bfloat162float(h[j]));
    }
    ((__nv_bfloat162*)hi)[2 * i]     = __nv_bfloat162(h[0], h[1]);
    ((__nv_bfloat162*)hi)[2 * i + 1] = __nv_bfloat162(h[2], h[3]);
    ((__nv_bfloat162*)lo)[2 * i]     = __nv_bfloat162(l[0], l[1]);
    ((__nv_bfloat162*)lo)[2 * i + 1] = __nv_bfloat162(l[2], l[3]);
}

// -------- per-token exact top-K + vote count + fused X bf16 split --------
// Row cached in dynamic smem; all radix passes and the count pass run from LDS.
#define TOPK_SMEM (N_NEU * 4 + 2048 * 4)   // row floats + histogram
__global__ void topk_count_kernel(const float* __restrict__ X,
                                  __nv_bfloat16* __restrict__ Xhi,
                                  __nv_bfloat16* __restrict__ Xlo) {
    extern __shared__ char dsm[];
    float* row = (float*)dsm;
    unsigned int* h = (unsigned int*)(dsm + N_NEU * 4);

    __shared__ unsigned int s_prefix;
    __shared__ int s_k;
    __shared__ int s_eq_n;
    __shared__ int s_eq_idx[64];

    const int t = blockIdx.x;
    const float* grow = X + (size_t)t * N_NEU;
    __nv_bfloat16* ghi = Xhi + (size_t)t * N_NEU;
    __nv_bfloat16* glo = Xlo + (size_t)t * N_NEU;

    if (threadIdx.x == 0) { s_prefix = 0u; s_k = K_TOK; s_eq_n = 0; }

    // load row to smem + write bf16 hi/lo split
    for (int j = threadIdx.x; j < N_NEU / 4; j += blockDim.x) {
        float4 v = ((const float4*)grow)[j];
        ((float4*)row)[j] = v;
        float a[4] = {v.x, v.y, v.z, v.w};
        __nv_bfloat16 hh[4], ll[4];
        #pragma unroll
        for (int q = 0; q < 4; q++) {
            hh[q] = __float2bfloat16_rn(a[q]);
            ll[q] = __float2bfloat16_rn(a[q] - __bfloat162float(hh[q]));
        }
        ((__nv_bfloat162*)ghi)[2 * j]     = __nv_bfloat162(hh[0], hh[1]);
        ((__nv_bfloat162*)ghi)[2 * j + 1] = __nv_bfloat162(hh[2], hh[3]);
        ((__nv_bfloat162*)glo)[2 * j]     = __nv_bfloat162(ll[0], ll[1]);
        ((__nv_bfloat162*)glo)[2 * j + 1] = __nv_bfloat162(ll[2], ll[3]);
    }
    __syncthreads();

    #pragma unroll
    for (int p = 0; p < 3; p++) {
        const int shift = (p == 0) ? 21 : (p == 1) ? 10 : 0;
        const int nbins = (p == 2) ? 1024 : 2048;
        const unsigned int himask =
            (p == 0) ? 0u : ((p == 1) ? (0xFFFFFFFFu << 21) : (0xFFFFFFFFu << 10));

        for (int i = threadIdx.x; i < nbins; i += blockDim.x) h[i] = 0u;
        __syncthreads();

        const unsigned int pre = s_prefix;
        for (int i = threadIdx.x; i < N_NEU; i += blockDim.x) {
            unsigned int u = fkey(row[i]);
            if ((u & himask) == pre)
                atomicAdd(&h[(u >> shift) & (unsigned)(nbins - 1)], 1u);
        }
        __syncthreads();

        if (threadIdx.x == 0) {
            int k = s_k, cum = 0, d = nbins - 1;
            for (; d > 0; d--) {
                if (cum + (int)h[d] >= k) break;
                cum += (int)h[d];
            }
            s_k = k - cum;
            s_prefix = pre | ((unsigned int)d << shift);
        }
        __syncthreads();
    }

    const unsigned int thr = s_prefix;
    const int m = s_k;

    for (int i = threadIdx.x; i < N_NEU; i += blockDim.x) {
        unsigned int u = fkey(row[i]);
        if (u > thr) {
            atomicAdd(&g_counts[i], 1);
        } else if (u == thr) {
            int p = atomicAdd(&s_eq_n, 1);
            if (p < 64) s_eq_idx[p] = i;
        }
    }
    __syncthreads();

    if (threadIdx.x == 0) {
        int n = s_eq_n; if (n > 64) n = 64;
        for (int a = 1; a < n; a++) {
            int v = s_eq_idx[a]; int b = a - 1;
            while (b >= 0 && s_eq_idx[b] > v) { s_eq_idx[b + 1] = s_eq_idx[b]; b--; }
            s_eq_idx[b + 1] = v;
        }
        int take = m; if (take > n) take = n;
        for (int j = 0; j < take; j++) atomicAdd(&g_counts[s_eq_idx[j]], 1);
    }
}

__global__ void hist_kernel() {
    int n = blockIdx.x * blockDim.x + threadIdx.x;
    if (n < N_NEU) atomicAdd(&g_hist[g_counts[n]], 1);
}

__global__ void scan_kernel() {
    __shared__ int sh[2049];
    for (int i = threadIdx.x; i < 2049; i += blockDim.x) sh[i] = g_hist[i];
    __syncthreads();
    if (threadIdx.x == 0) {
        int cum = 0;
        for (int c = 2048; c >= 0; c--) { g_off[c] = cum; cum += sh[c]; }
    }
}

__global__ void fill_kernel() {
    int n = blockIdx.x * blockDim.x + threadIdx.x;
    if (n < N_NEU) {
        int c = g_counts[n];
        int pos = g_off[c] + atomicAdd(&g_cursor[c], 1);
        g_scratch[pos] = n;
    }
}

__global__ void sort_kernel() {
    const int c = blockIdx.x;
    const int beg = g_off[c];
    const int cnt = g_hist[c];
    if (cnt <= 1) return;
    if (beg >= N_CORE) return;

    __shared__ int buf[2048];
    if (cnt <= 2048) {
        for (int i = threadIdx.x; i < cnt; i += blockDim.x) buf[i] = g_scratch[beg + i];
        __syncthreads();
        for (int ph = 0; ph < cnt; ph++) {
            int st = ph & 1;
            for (int i = threadIdx.x; st + 2 * i + 1 < cnt; i += blockDim.x) {
                int a = st + 2 * i;
                int u = buf[a], v = buf[a + 1];
                if (u > v) { buf[a] = v; buf[a + 1] = u; }
            }
            __syncthreads();
        }
        for (int i = threadIdx.x; i < cnt; i += blockDim.x) g_scratch[beg + i] = buf[i];
    } else {
        if (threadIdx.x == 0) {
            for (int a = beg + 1; a < beg + cnt; a++) {
                int v = g_scratch[a]; int b = a - 1;
                while (b >= beg && g_scratch[b] > v) { g_scratch[b + 1] = g_scratch[b]; b--; }
                g_scratch[b + 1] = v;
            }
        }
    }
}

__global__ void gather_kernel(const float* __restrict__ W, float* __restrict__ out2) {
    __shared__ float rowbuf[N_NEU];
    const int d = blockIdx.x;
    const float* wr = W + (size_t)d * N_NEU;
    for (int i = threadIdx.x; i < N_NEU / 4; i += blockDim.x)
        ((float4*)rowbuf)[i] = ((const float4*)wr)[i];
    __syncthreads();
    float* o = out2 + (size_t)d * N_CORE;
    for (int j = threadIdx.x; j < N_CORE; j += blockDim.x)
        o[j] = rowbuf[g_scratch[j]];
}

// ==================== mma.sync bf16x3 GEMM, BK=64, 2-stage cp.async ========
// 128x128 CTA tile, 8 warps (2M x 4N), warp tile 64x32.
// Per k-tile: 48 LDSM.x4 + 192 HMMA per warp, ONE __syncthreads.

#define GBM 128
#define GBN 128
#define GBK 64
#define ROWB 144                     // 128B data + 16B pad per smem row
#define ARR  (128 * ROWB)            // 18432 B per operand array
#define STG  (4 * ARR)               // 73728 B per stage (Ah, Al, Bh, Bl)
#define NSTG 2
#define GEMM_SMEM (NSTG * STG)       // 147456 B
#define OFF_AH 0
#define OFF_AL ARR
#define OFF_BH (2 * ARR)
#define OFF_BL (3 * ARR)
#define NIT (N_NEU / GBK)            // 172

__global__ __launch_bounds__(256, 1)
void gemm_mma_kernel(float* __restrict__ C) {
    extern __shared__ char smem[];
    const uint32_t sb0 = smem_u32(smem);

    const int tid  = threadIdx.x;
    const int lane = tid & 31;
    const int wid  = tid >> 5;
    const int wm   = (wid & 1) * 64;
    const int wn   = (wid >> 1) * 32;

    const int bt = blockIdx.y * GBM;
    const int bd = blockIdx.x * GBN;

    const __nv_bfloat16* Xh = g_Xhi;
    const __nv_bfloat16* Xl = g_Xlo;
    const __nv_bfloat16* Wh = g_Whi;
    const __nv_bfloat16* Wl = g_Wlo;

    // cp.async mapping: 1024 chunks per array, 4 per thread per array.
    // chunk q: row r = q>>3, chunk c = q&7 ; smem off = r*144 + c*16 ; gmem col = c*8
    auto load_stage = [&](int it, int s) {
        const uint32_t sb = sb0 + s * STG;
        const int k0 = it * GBK;
        #pragma unroll
        for (int i = 0; i < 4; i++) {
            const int q = i * 256 + tid;
            const int r = q >> 3, c = q & 7;
            const uint32_t o = (uint32_t)(r * ROWB + c * 16);
            const size_t gx = (size_t)(bt + r) * N_NEU + k0 + c * 8;
            const size_t gw = (size_t)(bd + r) * N_NEU + k0 + c * 8;
            cp_async16(sb + OFF_AH + o, Xh + gx);
            cp_async16(sb + OFF_AL + o, Xl + gx);
            cp_async16(sb + OFF_BH + o, Wh + gw);
            cp_async16(sb + OFF_BL + o, Wl + gw);
        }
        cp_commit();
    };

    float acc[4][4][4];
    #pragma unroll
    for (int i = 0; i < 4; i++)
        #pragma unroll
        for (int j = 0; j < 4; j++)
            #pragma unroll
            for (int r = 0; r < 4; r++) acc[i][j][r] = 0.0f;

    // ldmatrix per-lane address pieces
    const int mi = lane >> 3, ri = lane & 7;
    const uint32_t a_row_off = (uint32_t)((wm + (mi & 1) * 8 + ri) * ROWB + (mi >> 1) * 16);
    const uint32_t b_row_off = (uint32_t)((wn + (mi >> 1) * 8 + ri) * ROWB + (mi & 1) * 16);

    load_stage(0, 0);

    for (int it = 0; it < NIT; it++) {
        cp_wait0();                 // stage `it` landed
        __syncthreads();            // visible to all; stage it-1 buffer free

        if (it + 1 < NIT) load_stage(it + 1, (it + 1) & 1);

        const uint32_t sb = sb0 + (it & 1) * STG;
        const uint32_t aAh = sb + OFF_AH + a_row_off;
        const uint32_t aAl = sb + OFF_AL + a_row_off;
        const uint32_t aBh = sb + OFF_BH + b_row_off;
        const uint32_t aBl = sb + OFF_BL + b_row_off;

        #pragma unroll
        for (int ks = 0; ks < 4; ks++) {
            const uint32_t ko = ks * 32;
            uint32_t ah[4][4], al[4][4], bh[4][2], bl[4][2];
            #pragma unroll
            for (int mt = 0; mt < 4; mt++) {
                ldsm_x4(ah[mt][0], ah[mt][1], ah[mt][2], ah[mt][3],
                        aAh + ko + (uint32_t)(mt * 16 * ROWB));
                ldsm_x4(al[mt][0], al[mt][1], al[mt][2], al[mt][3],
                        aAl + ko + (uint32_t)(mt * 16 * ROWB));
            }
            #pragma unroll
            for (int ntp = 0; ntp < 2; ntp++) {
                ldsm_x4(bh[2 * ntp][0], bh[2 * ntp][1], bh[2 * ntp + 1][0], bh[2 * ntp + 1][1],
                        aBh + ko + (uint32_t)(ntp * 16 * ROWB));
                ldsm_x4(bl[2 * ntp][0], bl[2 * ntp][1], bl[2 * ntp + 1][0], bl[2 * ntp + 1][1],
                        aBl + ko + (uint32_t)(ntp * 16 * ROWB));
            }
            #pragma unroll
            for (int mt = 0; mt < 4; mt++)
                #pragma unroll
                for (int nt = 0; nt < 4; nt++) MMA_BF16(acc[mt][nt], ah[mt], bh[nt]);
            #pragma unroll
            for (int mt = 0; mt < 4; mt++)
                #pragma unroll
                for (int nt = 0; nt < 4; nt++) MMA_BF16(acc[mt][nt], ah[mt], bl[nt]);
            #pragma unroll
            for (int mt = 0; mt < 4; mt++)
                #pragma unroll
                for (int nt = 0; nt < 4; nt++) MMA_BF16(acc[mt][nt], al[mt], bh[nt]);
        }
        __syncthreads();            // all warps done with stage `it` before overwrite
    }

    // epilogue
    const int g   = lane >> 2;
    const int tig = lane & 3;
    #pragma unroll
    for (int mt = 0; mt < 4; mt++) {
        #pragma unroll
        for (int nt = 0; nt < 4; nt++) {
            int t0 = bt + wm + mt * 16 + g;
            int d0 = bd + wn + nt * 8 + tig * 2;
            float2 v0 = make_float2(acc[mt][nt][0], acc[mt][nt][1]);
            float2 v1 = make_float2(acc[mt][nt][2], acc[mt][nt][3]);
            *(float2*)(C + (size_t)t0 * D_OUT + d0)       = v0;
            *(float2*)(C + (size_t)(t0 + 8) * D_OUT + d0) = v1;
        }
    }
}

extern "C" void kernel_launch(void* const* d_in, const int* in_sizes, int n_in,
                              void* d_out, int out_size) {
    const float* X = (const float*)d_in[0];
    const float* W = (const float*)d_in[1];
    float* out = (float*)d_out;
    (void)in_sizes; (void)n_in; (void)out_size;

    cudaFuncSetAttribute(gemm_mma_kernel, cudaFuncAttributeMaxDynamicSharedMemorySize, GEMM_SMEM);
    cudaFuncSetAttribute(topk_count_kernel, cudaFuncAttributeMaxDynamicSharedMemorySize, TOPK_SMEM);

    __nv_bfloat16 *xh, *xl, *wh, *wl;
    cudaGetSymbolAddress((void**)&xh, g_Xhi);
    cudaGetSymbolAddress((void**)&xl, g_Xlo);
    cudaGetSymbolAddress((void**)&wh, g_Whi);
    cudaGetSymbolAddress((void**)&wl, g_Wlo);

    // W convert (X conversion fused into topk)
    const int nw4 = (D_OUT * N_NEU) / 4;
    convert_kernel<<<(nw4 + 255) / 256, 256>>>(W, wh, wl, nw4);

    // selection pipeline (+ X bf16 split)
    zero_kernel<<<43, 256>>>();
    topk_count_kernel<<<T_TOK, 256, TOPK_SMEM>>>(X, xh, xl);
    hist_kernel<<<43, 256>>>();
    scan_kernel<<<1, 256>>>();
    fill_kernel<<<43, 256>>>();
    sort_kernel<<<2049, 128>>>();

    // GEMM -> true_value
    dim3 ggrid(D_OUT / GBN, T_TOK / GBM);   // (32, 16)
    gemm_mma_kernel<<<ggrid, 256, GEMM_SMEM>>>(out);

    // filtered_W gather
    gather_kernel<<<D_OUT, 256>>>(W, out + (size_t)T_TOK * D_OUT);
}